// round 12
// baseline (speedup 1.0000x reference)
#include <cuda_runtime.h>
#include <cuda_bf16.h>
#include <math.h>
#include <stdint.h>

// Problem shape (fixed for this problem instance)
#define B_    4
#define NA    8192
#define NB_   8192
#define D_    256
#define TOPK  8
#define NCELL 512      // 8x8x8 grid of cells, cell side 16 (in //16 coords)

// ---------------------------------------------------------------------------
// Scratch (static device globals; no dynamic allocation allowed)
// ---------------------------------------------------------------------------
__device__ float g_P[B_ * NA * D_];        // af @ W1b^T + b1      [32768,256]
__device__ float g_Q[B_ * NB_ * D_];       // bf @ (W1a-W1b)^T     [32768,256]
__device__ float g_S[B_ * NA * D_];        // sum_k relu(Q+P)*dw   [32768,256]
__device__ float g_Wd[D_ * D_];            // [n=d][k=c] = w1[d,c]-w1[d,256+c] (tf32-rounded)
__device__ float g_W1b[D_ * D_];           // [n=d][k=c] = w1[d,256+c]         (tf32-rounded)
__device__ float g_W2r[D_ * D_];           // [n=e][k=d] = w2[e,d]             (tf32-rounded)
__device__ int   g_idx[B_ * NA * TOPK];
__device__ float g_dw[B_ * NA * TOPK];

// spatial grid scratch
__device__ int      g_cellcnt[B_ * NCELL];
__device__ int      g_cellstart[B_ * (NCELL + 1)];
__device__ int      g_cellcur[B_ * NCELL];
__device__ uint2    g_pts[B_ * NB_];       // cell-sorted (packed coord, index)
__device__ unsigned g_cbp[B_ * NB_];       // packed //16 coords, original order

// ---------------------------------------------------------------------------
// tf32 helpers
// ---------------------------------------------------------------------------
__device__ __forceinline__ unsigned f2tf32(float v) {
    unsigned r;
    asm("cvt.rna.tf32.f32 %0, %1;" : "=r"(r) : "f"(v));
    return r;
}

__device__ __forceinline__ void mma_tf32(float* c,
                                         unsigned a0, unsigned a1, unsigned a2, unsigned a3,
                                         unsigned b0, unsigned b1) {
    asm volatile(
        "mma.sync.aligned.m16n8k8.row.col.f32.tf32.tf32.f32 "
        "{%0,%1,%2,%3}, {%4,%5,%6,%7}, {%8,%9}, {%0,%1,%2,%3};"
        : "+f"(c[0]), "+f"(c[1]), "+f"(c[2]), "+f"(c[3])
        : "r"(a0), "r"(a1), "r"(a2), "r"(a3), "r"(b0), "r"(b1));
}

#define CP_ASYNC16(dst_u32, src_ptr) \
    asm volatile("cp.async.cg.shared.global [%0], [%1], 16;" \
                 :: "r"(dst_u32), "l"(src_ptr))
#define CP_COMMIT()  asm volatile("cp.async.commit_group;")
#define CP_WAIT1()   asm volatile("cp.async.wait_group 1;" ::: "memory")
#define CP_WAIT0()   asm volatile("cp.async.wait_group 0;" ::: "memory")

// ---------------------------------------------------------------------------
// Weight preprocessing: B operands ([n][k] row-major), tf32-rounded (rna) so
// the GEMM consumes B fragments without a cvt.
// ---------------------------------------------------------------------------
__global__ void prep_w_kernel(const float* __restrict__ w1,
                              const float* __restrict__ w2,
                              float* __restrict__ Wd,
                              float* __restrict__ W1b,
                              float* __restrict__ W2r) {
    int d = blockIdx.x;
    int c = threadIdx.x;
    float a = w1[d * 512 + c];
    float b = w1[d * 512 + 256 + c];
    Wd[d * 256 + c]  = __uint_as_float(f2tf32(a - b));
    W1b[d * 256 + c] = __uint_as_float(f2tf32(b));
    W2r[d * 256 + c] = __uint_as_float(f2tf32(w2[d * 256 + c]));
}

// ---------------------------------------------------------------------------
// Spatial grid build: zero -> histogram -> scan -> scatter
// ---------------------------------------------------------------------------
__global__ void zero_cnt_kernel(int* __restrict__ cnt) {
    cnt[blockIdx.x * blockDim.x + threadIdx.x] = 0;
}

__global__ void hist_kernel(const int* __restrict__ coords_b,
                            unsigned* __restrict__ cbp,
                            int* __restrict__ cnt) {
    const int i = blockIdx.x * blockDim.x + threadIdx.x;   // 0..B*NB-1
    const int b = i >> 13;
    const int* cb = coords_b + (size_t)i * 3;
    const unsigned x = ((unsigned)cb[0]) >> 4;
    const unsigned y = ((unsigned)cb[1]) >> 4;
    const unsigned z = ((unsigned)cb[2]) >> 4;
    cbp[i] = x | (y << 8) | (z << 16);
    const int cell = (int)(((x >> 4) << 6) | ((y >> 4) << 3) | (z >> 4));
    atomicAdd(&cnt[b * NCELL + cell], 1);
}

__global__ void scan_kernel(const int* __restrict__ cnt,
                            int* __restrict__ cellstart,
                            int* __restrict__ cur) {
    __shared__ int sc[NCELL];
    const int b = blockIdx.x, t = threadIdx.x;
    const int v = cnt[b * NCELL + t];
    sc[t] = v;
    __syncthreads();
    for (int off = 1; off < NCELL; off <<= 1) {
        int x = (t >= off) ? sc[t - off] : 0;
        __syncthreads();
        sc[t] += x;
        __syncthreads();
    }
    cellstart[b * (NCELL + 1) + t + 1] = sc[t];
    if (t == 0) cellstart[b * (NCELL + 1)] = 0;
    cur[b * NCELL + t] = sc[t] - v;   // exclusive
}

__global__ void scatter_kernel(const unsigned* __restrict__ cbp,
                               int* __restrict__ cur,
                               uint2* __restrict__ pts) {
    const int i = blockIdx.x * blockDim.x + threadIdx.x;
    const int b = i >> 13, j = i & 8191;
    const unsigned p = cbp[i];
    const int cell = (int)((((p >> 4) & 7u) << 6) | (((p >> 12) & 7u) << 3) | ((p >> 20) & 7u));
    const int pos = atomicAdd(&cur[b * NCELL + cell], 1);
    pts[(size_t)b * NB_ + pos] = make_uint2(p, (unsigned)j);
}

// ---------------------------------------------------------------------------
// kNN helpers
// ---------------------------------------------------------------------------
__device__ __forceinline__ void insert8(unsigned best[8], unsigned key) {
    if (key < best[7]) {
        best[7] = key;
#pragma unroll
        for (int t = 7; t > 0; --t) {
            unsigned lo = min(best[t - 1], best[t]);
            unsigned hi = max(best[t - 1], best[t]);
            best[t - 1] = lo;
            best[t]     = hi;
        }
    }
}

__device__ __forceinline__ unsigned merge8(unsigned best[8], int lane) {
    unsigned sel = 0;
#pragma unroll
    for (int r = 0; r < 8; ++r) {
        const unsigned v = best[0];
        const unsigned m = __reduce_min_sync(0xFFFFFFFFu, v);
        if (lane == r) sel = m;
        if (v == m) {
#pragma unroll
            for (int t = 0; t < 7; ++t) best[t] = best[t + 1];
            best[7] = 0xFFFFFFFFu;
        }
    }
    return sel;
}

// ---------------------------------------------------------------------------
// Grid kNN: one warp per query; certified exact (brute fallback if the 8th
// neighbor could lie outside the scanned neighborhood).
// ---------------------------------------------------------------------------
__global__ void knn_grid_kernel(const int* __restrict__ coords_a,
                                const unsigned* __restrict__ cbp,
                                const uint2* __restrict__ pts,
                                const int* __restrict__ cellstart,
                                int* __restrict__ idx_out,
                                float* __restrict__ dw_out) {
    const int b = blockIdx.y;
    const int warp = threadIdx.x >> 5;
    const int lane = threadIdx.x & 31;
    const int n = blockIdx.x * 8 + warp;

    const int* ca = coords_a + ((size_t)b * NA + n) * 3;
    const unsigned qx = ((unsigned)ca[0]) >> 4;
    const unsigned qy = ((unsigned)ca[1]) >> 4;
    const unsigned qz = ((unsigned)ca[2]) >> 4;
    const unsigned qp = qx | (qy << 8) | (qz << 16);

    const int cx = (int)(qx >> 4), cy = (int)(qy >> 4), cz = (int)(qz >> 4);
    const int x0 = max(cx - 1, 0), x1 = min(cx + 1, 7);
    const int y0 = max(cy - 1, 0), y1 = min(cy + 1, 7);
    const int z0 = max(cz - 1, 0), z1 = min(cz + 1, 7);

    const int sbase = b * (NCELL + 1);
    const uint2* ptsb = pts + (size_t)b * NB_;

    unsigned best[8];
#pragma unroll
    for (int t = 0; t < 8; ++t) best[t] = 0xFFFFFFFFu;

    for (int x = x0; x <= x1; ++x)
        for (int y = y0; y <= y1; ++y)
            for (int z = z0; z <= z1; ++z) {
                const int c = (x << 6) | (y << 3) | z;
                const int s = __ldg(&cellstart[sbase + c]);
                const int e = __ldg(&cellstart[sbase + c + 1]);
                for (int o = s + lane; o < e; o += 32) {
                    const uint2 pt = ptsb[o];
                    const unsigned ad = __vabsdiffu4(pt.x, qp);
                    const unsigned d2 = (unsigned)__dp4a((int)ad, (int)ad, 0);
                    insert8(best, (d2 << 13) | pt.y);
                }
            }

    unsigned sel = merge8(best, lane);

    const unsigned d2_8 = __shfl_sync(0xFFFFFFFFu, sel, 7) >> 13;
    int mo = 0x7FFFFFFF;
    if (x0 > 0) { int d = (int)qx - (16 * x0 - 1); mo = min(mo, d * d); }
    if (x1 < 7) { int d = 16 * (x1 + 1) - (int)qx; mo = min(mo, d * d); }
    if (y0 > 0) { int d = (int)qy - (16 * y0 - 1); mo = min(mo, d * d); }
    if (y1 < 7) { int d = 16 * (y1 + 1) - (int)qy; mo = min(mo, d * d); }
    if (z0 > 0) { int d = (int)qz - (16 * z0 - 1); mo = min(mo, d * d); }
    if (z1 < 7) { int d = 16 * (z1 + 1) - (int)qz; mo = min(mo, d * d); }

    if (d2_8 >= (unsigned)mo) {   // warp-uniform; vanishingly rare
#pragma unroll
        for (int t = 0; t < 8; ++t) best[t] = 0xFFFFFFFFu;
        const unsigned* cb = cbp + (size_t)b * NB_;
        for (int j = lane; j < NB_; j += 32) {
            const unsigned p = __ldg(&cb[j]);
            const unsigned ad = __vabsdiffu4(p, qp);
            const unsigned d2 = (unsigned)__dp4a((int)ad, (int)ad, 0);
            insert8(best, (d2 << 13) | (unsigned)j);
        }
        sel = merge8(best, lane);
    }

    if (lane < 8) {
        const int j = (int)(sel & 8191u);
        const float dist = sqrtf((float)(sel >> 13)) * (1.0f / 128.0f);
        const float dwv = 0.5f - fminf(dist, 0.5f);
        const size_t o = ((size_t)b * NA + n) * 8 + lane;
        idx_out[o] = j;
        dw_out[o]  = dwv;
    }
}

// ---------------------------------------------------------------------------
// TF32 mma GEMM: C[M,256] = A[M,256] @ Bw^T (+ bscale*bias)
//   Tile 64x128; 256 threads as 2(m) x 4(n) warps; warp tile 32x32; BK=32.
//   2-stage cp.async double buffer + REGISTER fragment double buffer:
//   k-step ks+1's fragments (and A cvt) load while ks's HMMAs issue, so
//   LDS latency overlaps tensor issue. HMMA order unchanged vs R11
//   (bit-identical numerics).
// ---------------------------------------------------------------------------
#define PAD  36
#define ASZ  (64 * PAD)     // 2304 words
#define BSZ  (128 * PAD)    // 4608 words
#define GEMM_SMEM (2 * (ASZ + BSZ) * 4)   // 55,296 bytes

__global__ __launch_bounds__(256, 3)
void mma_gemm_kernel(const float* __restrict__ A, const float* __restrict__ Bw,
                     float* __restrict__ C, int ldc,
                     const float* __restrict__ bias, float bscale) {
    extern __shared__ float sm[];
    float* As0 = sm;             // [2][ASZ]
    float* Bs0 = sm + 2 * ASZ;   // [2][BSZ]

    const int tid  = threadIdx.x;
    const int wid  = tid >> 5;
    const int lane = tid & 31;
    const int g    = lane >> 2;   // groupID 0..7
    const int t    = lane & 3;    // 0..3
    const int wm   = wid >> 2;    // 0..1 (32 rows each)
    const int wn   = wid & 3;     // 0..3 (32 cols each)

    const float* Ap = A  + (size_t)blockIdx.y * 64 * 256;
    const float* Bp = Bw + (size_t)blockIdx.x * 128 * 256;

    const int lrow = tid >> 3;          // 0..31
    const int lcol = (tid & 7) * 4;     // 0,4,...,28
    const uint32_t smA = (uint32_t)__cvta_generic_to_shared(As0);
    const uint32_t smB = (uint32_t)__cvta_generic_to_shared(Bs0);

    float acc[2][4][4];
#pragma unroll
    for (int i = 0; i < 2; ++i)
#pragma unroll
        for (int j = 0; j < 4; ++j)
#pragma unroll
            for (int r = 0; r < 4; ++r) acc[i][j][r] = 0.f;

#define PREFETCH(s) do {                                                        \
    const int k0_ = (s) * 32;                                                   \
    const uint32_t ab_ = smA + (((s) & 1) * ASZ) * 4;                           \
    const uint32_t bb_ = smB + (((s) & 1) * BSZ) * 4;                           \
    CP_ASYNC16(ab_ + (lrow * PAD + lcol) * 4,                                   \
               Ap + (size_t)lrow * 256 + k0_ + lcol);                           \
    CP_ASYNC16(ab_ + ((lrow + 32) * PAD + lcol) * 4,                            \
               Ap + (size_t)(lrow + 32) * 256 + k0_ + lcol);                    \
    _Pragma("unroll")                                                           \
    for (int i_ = 0; i_ < 4; ++i_)                                              \
        CP_ASYNC16(bb_ + ((lrow + 32 * i_) * PAD + lcol) * 4,                   \
                   Bp + (size_t)(lrow + 32 * i_) * 256 + k0_ + lcol);           \
} while (0)

// load fragments for k-step ks_ into register buffer buf_
#define LDFRAG(ks_, buf_) do {                                                  \
    const int kt_ = (ks_) * 8 + t;                                              \
    _Pragma("unroll")                                                           \
    for (int nt_ = 0; nt_ < 4; ++nt_) {                                         \
        const int n_ = wn * 32 + nt_ * 8 + g;                                   \
        fb0[buf_][nt_] = __float_as_uint(bs[n_ * PAD + kt_]);                   \
        fb1[buf_][nt_] = __float_as_uint(bs[n_ * PAD + kt_ + 4]);               \
    }                                                                           \
    _Pragma("unroll")                                                           \
    for (int mt_ = 0; mt_ < 2; ++mt_) {                                         \
        const int row_ = wm * 32 + mt_ * 16 + g;                                \
        fa[buf_][mt_][0] = f2tf32(as[row_ * PAD + kt_]);                        \
        fa[buf_][mt_][1] = f2tf32(as[(row_ + 8) * PAD + kt_]);                  \
        fa[buf_][mt_][2] = f2tf32(as[row_ * PAD + kt_ + 4]);                    \
        fa[buf_][mt_][3] = f2tf32(as[(row_ + 8) * PAD + kt_ + 4]);              \
    }                                                                           \
} while (0)

    PREFETCH(0);
    CP_COMMIT();

    for (int s = 0; s < 8; ++s) {
        if (s < 7) {
            PREFETCH(s + 1);    // into buf (s+1)&1
            CP_COMMIT();
            CP_WAIT1();         // stage s group complete; s+1 may be pending
        } else {
            CP_WAIT0();
        }
        __syncthreads();        // cross-thread smem visibility of stage s

        const float* as = As0 + (s & 1) * ASZ;
        const float* bs = Bs0 + (s & 1) * BSZ;

        unsigned fb0[2][4], fb1[2][4], fa[2][2][4];
        LDFRAG(0, 0);
#pragma unroll
        for (int ks = 0; ks < 4; ++ks) {
            if (ks < 3) LDFRAG(ks + 1, (ks + 1) & 1);   // prefetch next k-step
            const int bc = ks & 1;
#pragma unroll
            for (int mt = 0; mt < 2; ++mt)
#pragma unroll
                for (int nt = 0; nt < 4; ++nt)
                    mma_tf32(acc[mt][nt],
                             fa[bc][mt][0], fa[bc][mt][1], fa[bc][mt][2], fa[bc][mt][3],
                             fb0[bc][nt], fb1[bc][nt]);
        }
        __syncthreads();        // stage s fully consumed before buffer reuse
    }

    // epilogue
    const int rb = blockIdx.y * 64 + wm * 32;
    const int cb = blockIdx.x * 128 + wn * 32;
#pragma unroll
    for (int nt = 0; nt < 4; ++nt) {
        const int col = cb + nt * 8 + 2 * t;
        float b0 = bias ? bias[col] * bscale : 0.f;
        float b1 = bias ? bias[col + 1] * bscale : 0.f;
#pragma unroll
        for (int mt = 0; mt < 2; ++mt) {
            const int row = rb + mt * 16 + g;
            *(float2*)(C + (size_t)row * ldc + col) =
                make_float2(acc[mt][nt][0] + b0, acc[mt][nt][1] + b1);
            *(float2*)(C + (size_t)(row + 8) * ldc + col) =
                make_float2(acc[mt][nt][2] + b0, acc[mt][nt][3] + b1);
        }
    }
#undef PREFETCH
#undef LDFRAG
}

// ---------------------------------------------------------------------------
// Gather-reduce + a_feats copy:
//   S[q,:]        = sum_k relu(Q[b,idx_k,:] + P[q,:]) * dw_k
//   out[q, 0:256] = af[q,:]
// ---------------------------------------------------------------------------
__global__ void gather_reduce_copy_kernel(const float* __restrict__ P,
                                          const float* __restrict__ Q,
                                          const int* __restrict__ idx,
                                          const float* __restrict__ dw,
                                          const float* __restrict__ af,
                                          float* __restrict__ out,
                                          float* __restrict__ S) {
    const int tid = threadIdx.x;
    const int q = blockIdx.x * 4 + (tid >> 6);
    const int l = tid & 63;
    const int b = q >> 13;

    ((float4*)out)[(size_t)q * 128 + l] = ((const float4*)af)[(size_t)q * 64 + l];

    const float4* P4 = (const float4*)P;
    const float4* Q4 = (const float4*)Q + (size_t)b * NB_ * 64;

    const float4 p = P4[(size_t)q * 64 + l];
    float4 acc = make_float4(0.f, 0.f, 0.f, 0.f);

#pragma unroll
    for (int k = 0; k < 8; ++k) {
        const int   j = idx[(size_t)q * 8 + k];
        const float w = dw[(size_t)q * 8 + k];
        const float4 v = Q4[(size_t)j * 64 + l];
        acc.x += fmaxf(v.x + p.x, 0.f) * w;
        acc.y += fmaxf(v.y + p.y, 0.f) * w;
        acc.z += fmaxf(v.z + p.z, 0.f) * w;
        acc.w += fmaxf(v.w + p.w, 0.f) * w;
    }
    ((float4*)S)[(size_t)q * 64 + l] = acc;
}

// ---------------------------------------------------------------------------
extern "C" void kernel_launch(void* const* d_in, const int* in_sizes, int n_in,
                              void* d_out, int out_size) {
    const float* af = (const float*)d_in[0];
    const float* bf = (const float*)d_in[1];
    const int*   ca = (const int*)d_in[2];
    const int*   cb = (const int*)d_in[3];
    const float* w1 = (const float*)d_in[4];
    const float* b1 = (const float*)d_in[5];
    const float* w2 = (const float*)d_in[6];
    const float* b2 = (const float*)d_in[7];
    float* out = (float*)d_out;

    float *P, *Q, *S, *Wd, *W1b, *W2r, *dw;
    int *idx, *ccnt, *cstart, *ccur;
    uint2* pts;
    unsigned* cbp;
    cudaGetSymbolAddress((void**)&P,      g_P);
    cudaGetSymbolAddress((void**)&Q,      g_Q);
    cudaGetSymbolAddress((void**)&S,      g_S);
    cudaGetSymbolAddress((void**)&Wd,     g_Wd);
    cudaGetSymbolAddress((void**)&W1b,    g_W1b);
    cudaGetSymbolAddress((void**)&W2r,    g_W2r);
    cudaGetSymbolAddress((void**)&idx,    g_idx);
    cudaGetSymbolAddress((void**)&dw,     g_dw);
    cudaGetSymbolAddress((void**)&ccnt,   g_cellcnt);
    cudaGetSymbolAddress((void**)&cstart, g_cellstart);
    cudaGetSymbolAddress((void**)&ccur,   g_cellcur);
    cudaGetSymbolAddress((void**)&pts,    g_pts);
    cudaGetSymbolAddress((void**)&cbp,    g_cbp);

    cudaFuncSetAttribute(mma_gemm_kernel,
                         cudaFuncAttributeMaxDynamicSharedMemorySize, GEMM_SMEM);

    // One-time side-stream + events (host resources only; identical GPU work
    // on every call — the graph gets two parallel branches).
    static cudaStream_t s2 = nullptr;
    static cudaEvent_t ev_root = nullptr, ev_knn = nullptr;
    if (s2 == nullptr) {
        cudaStreamCreateWithFlags(&s2, cudaStreamNonBlocking);
        cudaEventCreateWithFlags(&ev_root, cudaEventDisableTiming);
        cudaEventCreateWithFlags(&ev_knn,  cudaEventDisableTiming);
    }

    // ---- fork: kNN branch on s2, GEMM branch on the main (default) stream
    cudaEventRecord(ev_root, 0);
    cudaStreamWaitEvent(s2, ev_root, 0);

    // branch A (s2): spatial grid build + exact certified kNN
    zero_cnt_kernel<<<B_, NCELL, 0, s2>>>(ccnt);
    hist_kernel<<<(B_ * NB_) / 256, 256, 0, s2>>>(cb, cbp, ccnt);
    scan_kernel<<<B_, NCELL, 0, s2>>>(ccnt, cstart, ccur);
    scatter_kernel<<<(B_ * NB_) / 256, 256, 0, s2>>>(cbp, ccur, pts);
    knn_grid_kernel<<<dim3(NA / 8, B_), 256, 0, s2>>>(ca, cbp, pts, cstart, idx, dw);
    cudaEventRecord(ev_knn, s2);

    // branch B (default stream): weight prep + P + Q
    prep_w_kernel<<<256, 256>>>(w1, w2, Wd, W1b, W2r);
    mma_gemm_kernel<<<dim3(2, (B_ * NA) / 64), 256, GEMM_SMEM>>>(af, W1b, P, 256, b1, 1.f);
    mma_gemm_kernel<<<dim3(2, (B_ * NB_) / 64), 256, GEMM_SMEM>>>(bf, Wd, Q, 256, (const float*)nullptr, 0.f);

    // ---- join, then gather + final GEMM
    cudaStreamWaitEvent(0, ev_knn, 0);
    gather_reduce_copy_kernel<<<(B_ * NA) / 4, 256>>>(P, Q, idx, dw, af, out, S);
    mma_gemm_kernel<<<dim3(2, (B_ * NA) / 64), 256, GEMM_SMEM>>>(S, W2r, out + 256, 512, b2, 8.f);
}

// round 13
// speedup vs baseline: 1.0123x; 1.0123x over previous
#include <cuda_runtime.h>
#include <cuda_bf16.h>
#include <math.h>
#include <stdint.h>

// Problem shape (fixed for this problem instance)
#define B_    4
#define NA    8192
#define NB_   8192
#define D_    256
#define TOPK  8
#define NCELL 512      // 8x8x8 grid of cells, cell side 16 (in //16 coords)

// ---------------------------------------------------------------------------
// Scratch (static device globals; no dynamic allocation allowed)
// ---------------------------------------------------------------------------
__device__ float g_P[B_ * NA * D_];        // af @ W1b^T + b1      [32768,256]
__device__ float g_Q[B_ * NB_ * D_];       // bf @ (W1a-W1b)^T     [32768,256]
__device__ float g_S[B_ * NA * D_];        // sum_k relu(Q+P)*dw   [32768,256]
__device__ float g_Wd[D_ * D_];            // [n=d][k=c] = w1[d,c]-w1[d,256+c]
__device__ float g_W1b[D_ * D_];           // [n=d][k=c] = w1[d,256+c]
__device__ float g_W2r[D_ * D_];           // [n=e][k=d] = w2[e,d]
__device__ int   g_idx[B_ * NA * TOPK];
__device__ float g_dw[B_ * NA * TOPK];

// spatial grid scratch
__device__ int      g_cellcnt[B_ * NCELL];
__device__ int      g_cellstart[B_ * (NCELL + 1)];
__device__ int      g_cellcur[B_ * NCELL];
__device__ uint2    g_pts[B_ * NB_];       // cell-sorted (packed coord, index)
__device__ unsigned g_cbp[B_ * NB_];       // packed //16 coords, original order

// ---------------------------------------------------------------------------
// fp16 helpers
// ---------------------------------------------------------------------------
// cvt.rn.f16x2.f32 d, a, b  =>  d.hi = a, d.lo = b  (verified operand order)
__device__ __forceinline__ unsigned pack_f16x2(float lo, float hi) {
    unsigned r;
    asm("cvt.rn.f16x2.f32 %0, %1, %2;" : "=r"(r) : "f"(hi), "f"(lo));
    return r;
}

__device__ __forceinline__ void mma_f16(float* c,
                                        unsigned a0, unsigned a1, unsigned a2, unsigned a3,
                                        unsigned b0, unsigned b1) {
    asm volatile(
        "mma.sync.aligned.m16n8k16.row.col.f32.f16.f16.f32 "
        "{%0,%1,%2,%3}, {%4,%5,%6,%7}, {%8,%9}, {%0,%1,%2,%3};"
        : "+f"(c[0]), "+f"(c[1]), "+f"(c[2]), "+f"(c[3])
        : "r"(a0), "r"(a1), "r"(a2), "r"(a3), "r"(b0), "r"(b1));
}

#define CP_ASYNC16(dst_u32, src_ptr) \
    asm volatile("cp.async.cg.shared.global [%0], [%1], 16;" \
                 :: "r"(dst_u32), "l"(src_ptr))
#define CP_COMMIT()  asm volatile("cp.async.commit_group;")
#define CP_WAIT1()   asm volatile("cp.async.wait_group 1;" ::: "memory")
#define CP_WAIT0()   asm volatile("cp.async.wait_group 0;" ::: "memory")

// ---------------------------------------------------------------------------
// Weight preprocessing: B operands ([n][k] row-major), plain fp32
// (fragment cvt does the rn fp16 rounding at consume time).
// ---------------------------------------------------------------------------
__global__ void prep_w_kernel(const float* __restrict__ w1,
                              const float* __restrict__ w2,
                              float* __restrict__ Wd,
                              float* __restrict__ W1b,
                              float* __restrict__ W2r) {
    int d = blockIdx.x;
    int c = threadIdx.x;
    float a = w1[d * 512 + c];
    float b = w1[d * 512 + 256 + c];
    Wd[d * 256 + c]  = a - b;
    W1b[d * 256 + c] = b;
    W2r[d * 256 + c] = w2[d * 256 + c];
}

// ---------------------------------------------------------------------------
// Spatial grid build: zero -> histogram -> scan -> scatter
// ---------------------------------------------------------------------------
__global__ void zero_cnt_kernel(int* __restrict__ cnt) {
    cnt[blockIdx.x * blockDim.x + threadIdx.x] = 0;
}

__global__ void hist_kernel(const int* __restrict__ coords_b,
                            unsigned* __restrict__ cbp,
                            int* __restrict__ cnt) {
    const int i = blockIdx.x * blockDim.x + threadIdx.x;   // 0..B*NB-1
    const int b = i >> 13;
    const int* cb = coords_b + (size_t)i * 3;
    const unsigned x = ((unsigned)cb[0]) >> 4;
    const unsigned y = ((unsigned)cb[1]) >> 4;
    const unsigned z = ((unsigned)cb[2]) >> 4;
    cbp[i] = x | (y << 8) | (z << 16);
    const int cell = (int)(((x >> 4) << 6) | ((y >> 4) << 3) | (z >> 4));
    atomicAdd(&cnt[b * NCELL + cell], 1);
}

__global__ void scan_kernel(const int* __restrict__ cnt,
                            int* __restrict__ cellstart,
                            int* __restrict__ cur) {
    __shared__ int sc[NCELL];
    const int b = blockIdx.x, t = threadIdx.x;
    const int v = cnt[b * NCELL + t];
    sc[t] = v;
    __syncthreads();
    for (int off = 1; off < NCELL; off <<= 1) {
        int x = (t >= off) ? sc[t - off] : 0;
        __syncthreads();
        sc[t] += x;
        __syncthreads();
    }
    cellstart[b * (NCELL + 1) + t + 1] = sc[t];
    if (t == 0) cellstart[b * (NCELL + 1)] = 0;
    cur[b * NCELL + t] = sc[t] - v;   // exclusive
}

__global__ void scatter_kernel(const unsigned* __restrict__ cbp,
                               int* __restrict__ cur,
                               uint2* __restrict__ pts) {
    const int i = blockIdx.x * blockDim.x + threadIdx.x;
    const int b = i >> 13, j = i & 8191;
    const unsigned p = cbp[i];
    const int cell = (int)((((p >> 4) & 7u) << 6) | (((p >> 12) & 7u) << 3) | ((p >> 20) & 7u));
    const int pos = atomicAdd(&cur[b * NCELL + cell], 1);
    pts[(size_t)b * NB_ + pos] = make_uint2(p, (unsigned)j);
}

// ---------------------------------------------------------------------------
// kNN helpers
// ---------------------------------------------------------------------------
__device__ __forceinline__ void insert8(unsigned best[8], unsigned key) {
    if (key < best[7]) {
        best[7] = key;
#pragma unroll
        for (int t = 7; t > 0; --t) {
            unsigned lo = min(best[t - 1], best[t]);
            unsigned hi = max(best[t - 1], best[t]);
            best[t - 1] = lo;
            best[t]     = hi;
        }
    }
}

__device__ __forceinline__ unsigned merge8(unsigned best[8], int lane) {
    unsigned sel = 0;
#pragma unroll
    for (int r = 0; r < 8; ++r) {
        const unsigned v = best[0];
        const unsigned m = __reduce_min_sync(0xFFFFFFFFu, v);
        if (lane == r) sel = m;
        if (v == m) {
#pragma unroll
            for (int t = 0; t < 7; ++t) best[t] = best[t + 1];
            best[7] = 0xFFFFFFFFu;
        }
    }
    return sel;
}

// ---------------------------------------------------------------------------
// Grid kNN: one warp per query; certified exact (brute fallback if the 8th
// neighbor could lie outside the scanned neighborhood).
// ---------------------------------------------------------------------------
__global__ void knn_grid_kernel(const int* __restrict__ coords_a,
                                const unsigned* __restrict__ cbp,
                                const uint2* __restrict__ pts,
                                const int* __restrict__ cellstart,
                                int* __restrict__ idx_out,
                                float* __restrict__ dw_out) {
    const int b = blockIdx.y;
    const int warp = threadIdx.x >> 5;
    const int lane = threadIdx.x & 31;
    const int n = blockIdx.x * 8 + warp;

    const int* ca = coords_a + ((size_t)b * NA + n) * 3;
    const unsigned qx = ((unsigned)ca[0]) >> 4;
    const unsigned qy = ((unsigned)ca[1]) >> 4;
    const unsigned qz = ((unsigned)ca[2]) >> 4;
    const unsigned qp = qx | (qy << 8) | (qz << 16);

    const int cx = (int)(qx >> 4), cy = (int)(qy >> 4), cz = (int)(qz >> 4);
    const int x0 = max(cx - 1, 0), x1 = min(cx + 1, 7);
    const int y0 = max(cy - 1, 0), y1 = min(cy + 1, 7);
    const int z0 = max(cz - 1, 0), z1 = min(cz + 1, 7);

    const int sbase = b * (NCELL + 1);
    const uint2* ptsb = pts + (size_t)b * NB_;

    unsigned best[8];
#pragma unroll
    for (int t = 0; t < 8; ++t) best[t] = 0xFFFFFFFFu;

    for (int x = x0; x <= x1; ++x)
        for (int y = y0; y <= y1; ++y)
            for (int z = z0; z <= z1; ++z) {
                const int c = (x << 6) | (y << 3) | z;
                const int s = __ldg(&cellstart[sbase + c]);
                const int e = __ldg(&cellstart[sbase + c + 1]);
                for (int o = s + lane; o < e; o += 32) {
                    const uint2 pt = ptsb[o];
                    const unsigned ad = __vabsdiffu4(pt.x, qp);
                    const unsigned d2 = (unsigned)__dp4a((int)ad, (int)ad, 0);
                    insert8(best, (d2 << 13) | pt.y);
                }
            }

    unsigned sel = merge8(best, lane);

    const unsigned d2_8 = __shfl_sync(0xFFFFFFFFu, sel, 7) >> 13;
    int mo = 0x7FFFFFFF;
    if (x0 > 0) { int d = (int)qx - (16 * x0 - 1); mo = min(mo, d * d); }
    if (x1 < 7) { int d = 16 * (x1 + 1) - (int)qx; mo = min(mo, d * d); }
    if (y0 > 0) { int d = (int)qy - (16 * y0 - 1); mo = min(mo, d * d); }
    if (y1 < 7) { int d = 16 * (y1 + 1) - (int)qy; mo = min(mo, d * d); }
    if (z0 > 0) { int d = (int)qz - (16 * z0 - 1); mo = min(mo, d * d); }
    if (z1 < 7) { int d = 16 * (z1 + 1) - (int)qz; mo = min(mo, d * d); }

    if (d2_8 >= (unsigned)mo) {   // warp-uniform; vanishingly rare
#pragma unroll
        for (int t = 0; t < 8; ++t) best[t] = 0xFFFFFFFFu;
        const unsigned* cb = cbp + (size_t)b * NB_;
        for (int j = lane; j < NB_; j += 32) {
            const unsigned p = __ldg(&cb[j]);
            const unsigned ad = __vabsdiffu4(p, qp);
            const unsigned d2 = (unsigned)__dp4a((int)ad, (int)ad, 0);
            insert8(best, (d2 << 13) | (unsigned)j);
        }
        sel = merge8(best, lane);
    }

    if (lane < 8) {
        const int j = (int)(sel & 8191u);
        const float dist = sqrtf((float)(sel >> 13)) * (1.0f / 128.0f);
        const float dwv = 0.5f - fminf(dist, 0.5f);
        const size_t o = ((size_t)b * NA + n) * 8 + lane;
        idx_out[o] = j;
        dw_out[o]  = dwv;
    }
}

// ---------------------------------------------------------------------------
// FP16 mma GEMM: C[M,256] = A[M,256] @ Bw^T (+ bscale*bias)
//   Bw: [256][256] row-major [n][k] fp32.
//   Tile 64x128; 256 threads as 2(m) x 4(n) warps; warp tile 32x32; BK=32.
//   m16n8k16.f16 (fp32 accum): 2 k-steps/stage, half the HMMAs of tf32.
//   Smem stays fp32; fragments via LDS.64 + cvt.rn.f16x2.f32.
//   PAD=40: (PAD/2) mod 16 = 4 -> 16 lanes of each LDS.64 phase hit 16
//   distinct bank-pairs (conflict-free); rows stay 16B-aligned for cp.async.
// ---------------------------------------------------------------------------
#define PAD  40
#define ASZ  (64 * PAD)     // 2560 words
#define BSZ  (128 * PAD)    // 5120 words
#define GEMM_SMEM (2 * (ASZ + BSZ) * 4)   // 61,440 bytes

__global__ __launch_bounds__(256, 3)
void mma_gemm_kernel(const float* __restrict__ A, const float* __restrict__ Bw,
                     float* __restrict__ C, int ldc,
                     const float* __restrict__ bias, float bscale) {
    extern __shared__ float sm[];
    float* As0 = sm;             // [2][ASZ]
    float* Bs0 = sm + 2 * ASZ;   // [2][BSZ]

    const int tid  = threadIdx.x;
    const int wid  = tid >> 5;
    const int lane = tid & 31;
    const int g    = lane >> 2;   // groupID 0..7
    const int t    = lane & 3;    // 0..3
    const int wm   = wid >> 2;    // 0..1 (32 rows each)
    const int wn   = wid & 3;     // 0..3 (32 cols each)

    const float* Ap = A  + (size_t)blockIdx.y * 64 * 256;
    const float* Bp = Bw + (size_t)blockIdx.x * 128 * 256;

    const int lrow = tid >> 3;          // 0..31
    const int lcol = (tid & 7) * 4;     // 0,4,...,28
    const uint32_t smA = (uint32_t)__cvta_generic_to_shared(As0);
    const uint32_t smB = (uint32_t)__cvta_generic_to_shared(Bs0);

    float acc[2][4][4];
#pragma unroll
    for (int i = 0; i < 2; ++i)
#pragma unroll
        for (int j = 0; j < 4; ++j)
#pragma unroll
            for (int r = 0; r < 4; ++r) acc[i][j][r] = 0.f;

#define PREFETCH(s) do {                                                        \
    const int k0_ = (s) * 32;                                                   \
    const uint32_t ab_ = smA + (((s) & 1) * ASZ) * 4;                           \
    const uint32_t bb_ = smB + (((s) & 1) * BSZ) * 4;                           \
    CP_ASYNC16(ab_ + (lrow * PAD + lcol) * 4,                                   \
               Ap + (size_t)lrow * 256 + k0_ + lcol);                           \
    CP_ASYNC16(ab_ + ((lrow + 32) * PAD + lcol) * 4,                            \
               Ap + (size_t)(lrow + 32) * 256 + k0_ + lcol);                    \
    _Pragma("unroll")                                                           \
    for (int i_ = 0; i_ < 4; ++i_)                                              \
        CP_ASYNC16(bb_ + ((lrow + 32 * i_) * PAD + lcol) * 4,                   \
                   Bp + (size_t)(lrow + 32 * i_) * 256 + k0_ + lcol);           \
} while (0)

    PREFETCH(0);
    CP_COMMIT();

    for (int s = 0; s < 8; ++s) {
        if (s < 7) {
            PREFETCH(s + 1);    // into buf (s+1)&1
            CP_COMMIT();
            CP_WAIT1();         // stage s group complete; s+1 may be pending
        } else {
            CP_WAIT0();
        }
        __syncthreads();        // cross-thread smem visibility of stage s

        const float* as = As0 + (s & 1) * ASZ;
        const float* bs = Bs0 + (s & 1) * BSZ;

#pragma unroll
        for (int ks = 0; ks < 2; ++ks) {
            const int kb = ks * 16 + 2 * t;   // this thread's k-pair base
            unsigned fb0[4], fb1[4];
#pragma unroll
            for (int nt = 0; nt < 4; ++nt) {
                const int n = wn * 32 + nt * 8 + g;
                const float2 blo = *(const float2*)&bs[n * PAD + kb];
                const float2 bhi = *(const float2*)&bs[n * PAD + kb + 8];
                fb0[nt] = pack_f16x2(blo.x, blo.y);
                fb1[nt] = pack_f16x2(bhi.x, bhi.y);
            }
#pragma unroll
            for (int mt = 0; mt < 2; ++mt) {
                const int row = wm * 32 + mt * 16 + g;
                const float2 a00 = *(const float2*)&as[row * PAD + kb];
                const float2 a10 = *(const float2*)&as[(row + 8) * PAD + kb];
                const float2 a01 = *(const float2*)&as[row * PAD + kb + 8];
                const float2 a11 = *(const float2*)&as[(row + 8) * PAD + kb + 8];
                const unsigned a0 = pack_f16x2(a00.x, a00.y);
                const unsigned a1 = pack_f16x2(a10.x, a10.y);
                const unsigned a2 = pack_f16x2(a01.x, a01.y);
                const unsigned a3 = pack_f16x2(a11.x, a11.y);
#pragma unroll
                for (int nt = 0; nt < 4; ++nt)
                    mma_f16(acc[mt][nt], a0, a1, a2, a3, fb0[nt], fb1[nt]);
            }
        }
        __syncthreads();        // stage s fully consumed before buffer reuse
    }

    // epilogue
    const int rb = blockIdx.y * 64 + wm * 32;
    const int cb = blockIdx.x * 128 + wn * 32;
#pragma unroll
    for (int nt = 0; nt < 4; ++nt) {
        const int col = cb + nt * 8 + 2 * t;
        float b0 = bias ? bias[col] * bscale : 0.f;
        float b1 = bias ? bias[col + 1] * bscale : 0.f;
#pragma unroll
        for (int mt = 0; mt < 2; ++mt) {
            const int row = rb + mt * 16 + g;
            *(float2*)(C + (size_t)row * ldc + col) =
                make_float2(acc[mt][nt][0] + b0, acc[mt][nt][1] + b1);
            *(float2*)(C + (size_t)(row + 8) * ldc + col) =
                make_float2(acc[mt][nt][2] + b0, acc[mt][nt][3] + b1);
        }
    }
#undef PREFETCH
}

// ---------------------------------------------------------------------------
// Gather-reduce + a_feats copy:
//   S[q,:]        = sum_k relu(Q[b,idx_k,:] + P[q,:]) * dw_k
//   out[q, 0:256] = af[q,:]
// ---------------------------------------------------------------------------
__global__ void gather_reduce_copy_kernel(const float* __restrict__ P,
                                          const float* __restrict__ Q,
                                          const int* __restrict__ idx,
                                          const float* __restrict__ dw,
                                          const float* __restrict__ af,
                                          float* __restrict__ out,
                                          float* __restrict__ S) {
    const int tid = threadIdx.x;
    const int q = blockIdx.x * 4 + (tid >> 6);
    const int l = tid & 63;
    const int b = q >> 13;

    ((float4*)out)[(size_t)q * 128 + l] = ((const float4*)af)[(size_t)q * 64 + l];

    const float4* P4 = (const float4*)P;
    const float4* Q4 = (const float4*)Q + (size_t)b * NB_ * 64;

    const float4 p = P4[(size_t)q * 64 + l];
    float4 acc = make_float4(0.f, 0.f, 0.f, 0.f);

#pragma unroll
    for (int k = 0; k < 8; ++k) {
        const int   j = idx[(size_t)q * 8 + k];
        const float w = dw[(size_t)q * 8 + k];
        const float4 v = Q4[(size_t)j * 64 + l];
        acc.x += fmaxf(v.x + p.x, 0.f) * w;
        acc.y += fmaxf(v.y + p.y, 0.f) * w;
        acc.z += fmaxf(v.z + p.z, 0.f) * w;
        acc.w += fmaxf(v.w + p.w, 0.f) * w;
    }
    ((float4*)S)[(size_t)q * 64 + l] = acc;
}

// ---------------------------------------------------------------------------
extern "C" void kernel_launch(void* const* d_in, const int* in_sizes, int n_in,
                              void* d_out, int out_size) {
    const float* af = (const float*)d_in[0];
    const float* bf = (const float*)d_in[1];
    const int*   ca = (const int*)d_in[2];
    const int*   cb = (const int*)d_in[3];
    const float* w1 = (const float*)d_in[4];
    const float* b1 = (const float*)d_in[5];
    const float* w2 = (const float*)d_in[6];
    const float* b2 = (const float*)d_in[7];
    float* out = (float*)d_out;

    float *P, *Q, *S, *Wd, *W1b, *W2r, *dw;
    int *idx, *ccnt, *cstart, *ccur;
    uint2* pts;
    unsigned* cbp;
    cudaGetSymbolAddress((void**)&P,      g_P);
    cudaGetSymbolAddress((void**)&Q,      g_Q);
    cudaGetSymbolAddress((void**)&S,      g_S);
    cudaGetSymbolAddress((void**)&Wd,     g_Wd);
    cudaGetSymbolAddress((void**)&W1b,    g_W1b);
    cudaGetSymbolAddress((void**)&W2r,    g_W2r);
    cudaGetSymbolAddress((void**)&idx,    g_idx);
    cudaGetSymbolAddress((void**)&dw,     g_dw);
    cudaGetSymbolAddress((void**)&ccnt,   g_cellcnt);
    cudaGetSymbolAddress((void**)&cstart, g_cellstart);
    cudaGetSymbolAddress((void**)&ccur,   g_cellcur);
    cudaGetSymbolAddress((void**)&pts,    g_pts);
    cudaGetSymbolAddress((void**)&cbp,    g_cbp);

    cudaFuncSetAttribute(mma_gemm_kernel,
                         cudaFuncAttributeMaxDynamicSharedMemorySize, GEMM_SMEM);

    // 1. spatial grid build
    zero_cnt_kernel<<<B_, NCELL>>>(ccnt);
    hist_kernel<<<(B_ * NB_) / 256, 256>>>(cb, cbp, ccnt);
    scan_kernel<<<B_, NCELL>>>(ccnt, cstart, ccur);
    scatter_kernel<<<(B_ * NB_) / 256, 256>>>(cbp, ccur, pts);

    // 2. exact certified grid kNN
    knn_grid_kernel<<<dim3(NA / 8, B_), 256>>>(ca, cbp, pts, cstart, idx, dw);

    // 3. weight prep ([n][k] B operands)
    prep_w_kernel<<<256, 256>>>(w1, w2, Wd, W1b, W2r);

    // 4. P = af @ W1b^T + b1
    mma_gemm_kernel<<<dim3(2, (B_ * NA) / 64), 256, GEMM_SMEM>>>(af, W1b, P, 256, b1, 1.f);

    // 5. Q = bf @ Wd^T
    mma_gemm_kernel<<<dim3(2, (B_ * NB_) / 64), 256, GEMM_SMEM>>>(bf, Wd, Q, 256, (const float*)nullptr, 0.f);

    // 6. S = sum_k relu(Q[idx_k] + P) * dw_k ; out[...,0:256] = af
    gather_reduce_copy_kernel<<<(B_ * NA) / 4, 256>>>(P, Q, idx, dw, af, out, S);

    // 7. out[..., 256:512] = S @ W2r^T + 8*b2
    mma_gemm_kernel<<<dim3(2, (B_ * NA) / 64), 256, GEMM_SMEM>>>(S, W2r, out + 256, 512, b2, 8.f);
}

// round 14
// speedup vs baseline: 1.5902x; 1.5708x over previous
#include <cuda_runtime.h>
#include <cuda_fp16.h>
#include <math.h>
#include <stdint.h>

// Problem shape (fixed for this problem instance)
#define B_    4
#define NA    8192
#define NB_   8192
#define D_    256
#define TOPK  8
#define NCELL 512      // 8x8x8 grid of cells, cell side 16 (in //16 coords)

// ---------------------------------------------------------------------------
// Scratch (static device globals; no dynamic allocation allowed)
// ---------------------------------------------------------------------------
__device__ float  g_P[B_ * NA * D_];       // af @ W1b^T + b1      [32768,256] f32
__device__ float  g_Q[B_ * NB_ * D_];      // bf @ (W1a-W1b)^T     [32768,256] f32
__device__ __half g_afh[B_ * NA * D_];     // fp16 copy of a_feats
__device__ __half g_bfh[B_ * NB_ * D_];    // fp16 copy of b_feats
__device__ __half g_Sh[B_ * NA * D_];      // gather result, fp16
__device__ __half g_Wdh[D_ * D_];          // [n=d][k=c] = w1[d,c]-w1[d,256+c]
__device__ __half g_W1bh[D_ * D_];         // [n=d][k=c] = w1[d,256+c]
__device__ __half g_W2h[D_ * D_];          // [n=e][k=d] = w2[e,d]
__device__ int    g_idx[B_ * NA * TOPK];
__device__ float  g_dw[B_ * NA * TOPK];

// spatial grid scratch
__device__ int      g_cellcnt[B_ * NCELL];
__device__ int      g_cellstart[B_ * (NCELL + 1)];
__device__ int      g_cellcur[B_ * NCELL];
__device__ uint2    g_pts[B_ * NB_];       // cell-sorted (packed coord, index)
__device__ unsigned g_cbp[B_ * NB_];       // packed //16 coords, original order

// ---------------------------------------------------------------------------
// mma / ldmatrix / cp.async helpers
// ---------------------------------------------------------------------------
__device__ __forceinline__ void mma_f16(float* c,
                                        unsigned a0, unsigned a1, unsigned a2, unsigned a3,
                                        unsigned b0, unsigned b1) {
    asm volatile(
        "mma.sync.aligned.m16n8k16.row.col.f32.f16.f16.f32 "
        "{%0,%1,%2,%3}, {%4,%5,%6,%7}, {%8,%9}, {%0,%1,%2,%3};"
        : "+f"(c[0]), "+f"(c[1]), "+f"(c[2]), "+f"(c[3])
        : "r"(a0), "r"(a1), "r"(a2), "r"(a3), "r"(b0), "r"(b1));
}

#define LDMATRIX_X4(r0, r1, r2, r3, addr) \
    asm volatile("ldmatrix.sync.aligned.m8n8.x4.shared.b16 {%0,%1,%2,%3}, [%4];" \
                 : "=r"(r0), "=r"(r1), "=r"(r2), "=r"(r3) : "r"(addr))

#define CP_ASYNC16(dst_u32, src_ptr) \
    asm volatile("cp.async.cg.shared.global [%0], [%1], 16;" \
                 :: "r"(dst_u32), "l"(src_ptr))
#define CP_COMMIT()  asm volatile("cp.async.commit_group;")
#define CP_WAIT1()   asm volatile("cp.async.wait_group 1;" ::: "memory")
#define CP_WAIT0()   asm volatile("cp.async.wait_group 0;" ::: "memory")

// ---------------------------------------------------------------------------
// fp32 -> fp16 convert (af / bf): n multiple of 1024, float4 granularity
// ---------------------------------------------------------------------------
__global__ void f32_to_f16_kernel(const float4* __restrict__ src,
                                  __half2* __restrict__ dst) {
    const int i = blockIdx.x * blockDim.x + threadIdx.x;
    const float4 v = src[i];
    dst[2 * i]     = __floats2half2_rn(v.x, v.y);
    dst[2 * i + 1] = __floats2half2_rn(v.z, v.w);
}

// ---------------------------------------------------------------------------
// Weight preprocessing: fp16 B operands ([n][k] row-major)
// ---------------------------------------------------------------------------
__global__ void prep_w_kernel(const float* __restrict__ w1,
                              const float* __restrict__ w2,
                              __half* __restrict__ Wdh,
                              __half* __restrict__ W1bh,
                              __half* __restrict__ W2h) {
    int d = blockIdx.x;
    int c = threadIdx.x;
    float a = w1[d * 512 + c];
    float b = w1[d * 512 + 256 + c];
    Wdh[d * 256 + c]  = __float2half_rn(a - b);
    W1bh[d * 256 + c] = __float2half_rn(b);
    W2h[d * 256 + c]  = __float2half_rn(w2[d * 256 + c]);
}

// ---------------------------------------------------------------------------
// Spatial grid build: zero -> histogram -> scan -> scatter
// ---------------------------------------------------------------------------
__global__ void zero_cnt_kernel(int* __restrict__ cnt) {
    cnt[blockIdx.x * blockDim.x + threadIdx.x] = 0;
}

__global__ void hist_kernel(const int* __restrict__ coords_b,
                            unsigned* __restrict__ cbp,
                            int* __restrict__ cnt) {
    const int i = blockIdx.x * blockDim.x + threadIdx.x;   // 0..B*NB-1
    const int b = i >> 13;
    const int* cb = coords_b + (size_t)i * 3;
    const unsigned x = ((unsigned)cb[0]) >> 4;
    const unsigned y = ((unsigned)cb[1]) >> 4;
    const unsigned z = ((unsigned)cb[2]) >> 4;
    cbp[i] = x | (y << 8) | (z << 16);
    const int cell = (int)(((x >> 4) << 6) | ((y >> 4) << 3) | (z >> 4));
    atomicAdd(&cnt[b * NCELL + cell], 1);
}

__global__ void scan_kernel(const int* __restrict__ cnt,
                            int* __restrict__ cellstart,
                            int* __restrict__ cur) {
    __shared__ int sc[NCELL];
    const int b = blockIdx.x, t = threadIdx.x;
    const int v = cnt[b * NCELL + t];
    sc[t] = v;
    __syncthreads();
    for (int off = 1; off < NCELL; off <<= 1) {
        int x = (t >= off) ? sc[t - off] : 0;
        __syncthreads();
        sc[t] += x;
        __syncthreads();
    }
    cellstart[b * (NCELL + 1) + t + 1] = sc[t];
    if (t == 0) cellstart[b * (NCELL + 1)] = 0;
    cur[b * NCELL + t] = sc[t] - v;   // exclusive
}

__global__ void scatter_kernel(const unsigned* __restrict__ cbp,
                               int* __restrict__ cur,
                               uint2* __restrict__ pts) {
    const int i = blockIdx.x * blockDim.x + threadIdx.x;
    const int b = i >> 13, j = i & 8191;
    const unsigned p = cbp[i];
    const int cell = (int)((((p >> 4) & 7u) << 6) | (((p >> 12) & 7u) << 3) | ((p >> 20) & 7u));
    const int pos = atomicAdd(&cur[b * NCELL + cell], 1);
    pts[(size_t)b * NB_ + pos] = make_uint2(p, (unsigned)j);
}

// ---------------------------------------------------------------------------
// kNN helpers
// ---------------------------------------------------------------------------
__device__ __forceinline__ void insert8(unsigned best[8], unsigned key) {
    if (key < best[7]) {
        best[7] = key;
#pragma unroll
        for (int t = 7; t > 0; --t) {
            unsigned lo = min(best[t - 1], best[t]);
            unsigned hi = max(best[t - 1], best[t]);
            best[t - 1] = lo;
            best[t]     = hi;
        }
    }
}

__device__ __forceinline__ unsigned merge8(unsigned best[8], int lane) {
    unsigned sel = 0;
#pragma unroll
    for (int r = 0; r < 8; ++r) {
        const unsigned v = best[0];
        const unsigned m = __reduce_min_sync(0xFFFFFFFFu, v);
        if (lane == r) sel = m;
        if (v == m) {
#pragma unroll
            for (int t = 0; t < 7; ++t) best[t] = best[t + 1];
            best[7] = 0xFFFFFFFFu;
        }
    }
    return sel;
}

// ---------------------------------------------------------------------------
// Grid kNN: one warp per query; certified exact (brute fallback if the 8th
// neighbor could lie outside the scanned neighborhood).
// ---------------------------------------------------------------------------
__global__ void knn_grid_kernel(const int* __restrict__ coords_a,
                                const unsigned* __restrict__ cbp,
                                const uint2* __restrict__ pts,
                                const int* __restrict__ cellstart,
                                int* __restrict__ idx_out,
                                float* __restrict__ dw_out) {
    const int b = blockIdx.y;
    const int warp = threadIdx.x >> 5;
    const int lane = threadIdx.x & 31;
    const int n = blockIdx.x * 8 + warp;

    const int* ca = coords_a + ((size_t)b * NA + n) * 3;
    const unsigned qx = ((unsigned)ca[0]) >> 4;
    const unsigned qy = ((unsigned)ca[1]) >> 4;
    const unsigned qz = ((unsigned)ca[2]) >> 4;
    const unsigned qp = qx | (qy << 8) | (qz << 16);

    const int cx = (int)(qx >> 4), cy = (int)(qy >> 4), cz = (int)(qz >> 4);
    const int x0 = max(cx - 1, 0), x1 = min(cx + 1, 7);
    const int y0 = max(cy - 1, 0), y1 = min(cy + 1, 7);
    const int z0 = max(cz - 1, 0), z1 = min(cz + 1, 7);

    const int sbase = b * (NCELL + 1);
    const uint2* ptsb = pts + (size_t)b * NB_;

    unsigned best[8];
#pragma unroll
    for (int t = 0; t < 8; ++t) best[t] = 0xFFFFFFFFu;

    for (int x = x0; x <= x1; ++x)
        for (int y = y0; y <= y1; ++y)
            for (int z = z0; z <= z1; ++z) {
                const int c = (x << 6) | (y << 3) | z;
                const int s = __ldg(&cellstart[sbase + c]);
                const int e = __ldg(&cellstart[sbase + c + 1]);
                for (int o = s + lane; o < e; o += 32) {
                    const uint2 pt = ptsb[o];
                    const unsigned ad = __vabsdiffu4(pt.x, qp);
                    const unsigned d2 = (unsigned)__dp4a((int)ad, (int)ad, 0);
                    insert8(best, (d2 << 13) | pt.y);
                }
            }

    unsigned sel = merge8(best, lane);

    const unsigned d2_8 = __shfl_sync(0xFFFFFFFFu, sel, 7) >> 13;
    int mo = 0x7FFFFFFF;
    if (x0 > 0) { int d = (int)qx - (16 * x0 - 1); mo = min(mo, d * d); }
    if (x1 < 7) { int d = 16 * (x1 + 1) - (int)qx; mo = min(mo, d * d); }
    if (y0 > 0) { int d = (int)qy - (16 * y0 - 1); mo = min(mo, d * d); }
    if (y1 < 7) { int d = 16 * (y1 + 1) - (int)qy; mo = min(mo, d * d); }
    if (z0 > 0) { int d = (int)qz - (16 * z0 - 1); mo = min(mo, d * d); }
    if (z1 < 7) { int d = 16 * (z1 + 1) - (int)qz; mo = min(mo, d * d); }

    if (d2_8 >= (unsigned)mo) {   // warp-uniform; vanishingly rare
#pragma unroll
        for (int t = 0; t < 8; ++t) best[t] = 0xFFFFFFFFu;
        const unsigned* cb = cbp + (size_t)b * NB_;
        for (int j = lane; j < NB_; j += 32) {
            const unsigned p = __ldg(&cb[j]);
            const unsigned ad = __vabsdiffu4(p, qp);
            const unsigned d2 = (unsigned)__dp4a((int)ad, (int)ad, 0);
            insert8(best, (d2 << 13) | (unsigned)j);
        }
        sel = merge8(best, lane);
    }

    if (lane < 8) {
        const int j = (int)(sel & 8191u);
        const float dist = sqrtf((float)(sel >> 13)) * (1.0f / 128.0f);
        const float dwv = 0.5f - fminf(dist, 0.5f);
        const size_t o = ((size_t)b * NA + n) * 8 + lane;
        idx_out[o] = j;
        dw_out[o]  = dwv;
    }
}

// ---------------------------------------------------------------------------
// FP16 ldmatrix GEMM: C[M,256] = Ah[M,256] @ Bh^T (+ bscale*bias), fp32 accum
//   Ah: fp16 row-major [m][k]. Bh: fp16 row-major [n][k].
//   Tile 64x128; 256 threads as 2(m) x 4(n) warps; warp tile 32x32; BK=64.
//   Smem fp16, row stride 72 halves (144B): ldmatrix 8-row phases step the
//   16B-chunk index by 9 = 1 (mod 8) -> conflict-free.
//   Per warp-stage: 16 ldmatrix.x4 + 32 HMMA.16816 (2:1 HMMA:aux).
// ---------------------------------------------------------------------------
#define SRH   72                  // smem row stride in halves
#define A_STB (64 * SRH * 2)      // 9216 B per A stage
#define B_STB (128 * SRH * 2)     // 18432 B per B stage
#define GEMM_SMEM (2 * (A_STB + B_STB))   // 55296 B

__global__ __launch_bounds__(256, 3)
void mma_gemm_kernel(const __half* __restrict__ Ah, const __half* __restrict__ Bh,
                     float* __restrict__ C, int ldc,
                     const float* __restrict__ bias, float bscale) {
    extern __shared__ char smc[];
    // layout: [A buf0][A buf1][B buf0][B buf1]
    const uint32_t smA = (uint32_t)__cvta_generic_to_shared(smc);
    const uint32_t smB = smA + 2 * A_STB;

    const int tid  = threadIdx.x;
    const int wid  = tid >> 5;
    const int lane = tid & 31;
    const int g    = lane >> 2;   // groupID 0..7
    const int t    = lane & 3;    // 0..3
    const int wm   = wid >> 2;    // 0..1 (32 rows each)
    const int wn   = wid & 3;     // 0..3 (32 cols each)

    const __half* Ap = Ah + (size_t)blockIdx.y * 64 * 256;
    const __half* Bp = Bh + (size_t)blockIdx.x * 128 * 256;

    // loader: 16B = 8-half chunks. A: 512 chunks (2/thread), B: 1024 (4/thread)
    const int arow0 = tid >> 3,           ac0 = (tid & 7) * 8;
    const int arow1 = (tid + 256) >> 3,   ac1 = ac0;      // same column pattern

    // ldmatrix per-lane address components
    const int sel = lane >> 3;            // 0..3 (x4 tile select)
    const int lr  = lane & 7;             // row within tile
    // A x4 covering (mt 16m) x (16k): tiles m0-7/k0, m8-15/k0, m0-7/k8, m8-15/k8
    const int a_row_off = (sel & 1) * 8 + lr;     // + wm*32 + mt*16
    const int a_k_off   = (sel >> 1) * 8;         // + ks*16
    // B x4 covering (2 n-tiles) x (16k): tiles n0/k0, n0/k8, n1/k0, n1/k8
    const int b_n_off = (sel >> 1) * 8 + lr;      // + wn*32 + p*16
    const int b_k_off = (sel & 1) * 8;            // + ks*16

    float acc[2][4][4];
#pragma unroll
    for (int i = 0; i < 2; ++i)
#pragma unroll
        for (int j = 0; j < 4; ++j)
#pragma unroll
            for (int r = 0; r < 4; ++r) acc[i][j][r] = 0.f;

#define PREFETCH(s) do {                                                        \
    const int k0_ = (s) * 64;                                                   \
    const uint32_t ab_ = smA + ((s) & 1) * A_STB;                               \
    const uint32_t bb_ = smB + ((s) & 1) * B_STB;                               \
    CP_ASYNC16(ab_ + (arow0 * SRH + ac0) * 2, Ap + (size_t)arow0 * 256 + k0_ + ac0); \
    CP_ASYNC16(ab_ + (arow1 * SRH + ac1) * 2, Ap + (size_t)arow1 * 256 + k0_ + ac1); \
    _Pragma("unroll")                                                           \
    for (int i_ = 0; i_ < 4; ++i_) {                                            \
        const int id_ = tid + 256 * i_;                                         \
        const int br_ = id_ >> 3, bc_ = (id_ & 7) * 8;                          \
        CP_ASYNC16(bb_ + (br_ * SRH + bc_) * 2, Bp + (size_t)br_ * 256 + k0_ + bc_); \
    }                                                                           \
} while (0)

    PREFETCH(0);
    CP_COMMIT();

    for (int s = 0; s < 4; ++s) {
        if (s < 3) {
            PREFETCH(s + 1);
            CP_COMMIT();
            CP_WAIT1();
        } else {
            CP_WAIT0();
        }
        __syncthreads();

        const uint32_t as = smA + (s & 1) * A_STB;
        const uint32_t bs = smB + (s & 1) * B_STB;

#pragma unroll
        for (int ks = 0; ks < 4; ++ks) {
            // B fragments: 2 ldmatrix.x4 cover nt 0..3 (b0,b1 each)
            unsigned fb0[4], fb1[4];
#pragma unroll
            for (int p = 0; p < 2; ++p) {
                const int nrow = wn * 32 + p * 16 + b_n_off;
                const uint32_t addr = bs + (nrow * SRH + ks * 16 + b_k_off) * 2;
                unsigned r0, r1, r2, r3;
                LDMATRIX_X4(r0, r1, r2, r3, addr);
                fb0[2 * p]     = r0;  fb1[2 * p]     = r1;
                fb0[2 * p + 1] = r2;  fb1[2 * p + 1] = r3;
            }
            // A fragments + MMAs per mt
#pragma unroll
            for (int mt = 0; mt < 2; ++mt) {
                const int arow = wm * 32 + mt * 16 + a_row_off;
                const uint32_t addr = as + (arow * SRH + ks * 16 + a_k_off) * 2;
                unsigned a0, a1, a2, a3;
                LDMATRIX_X4(a0, a1, a2, a3, addr);
#pragma unroll
                for (int nt = 0; nt < 4; ++nt)
                    mma_f16(acc[mt][nt], a0, a1, a2, a3, fb0[nt], fb1[nt]);
            }
        }
        __syncthreads();
    }

    // epilogue (same C layout as m16n8k8)
    const int rb = blockIdx.y * 64 + wm * 32;
    const int cb = blockIdx.x * 128 + wn * 32;
#pragma unroll
    for (int nt = 0; nt < 4; ++nt) {
        const int col = cb + nt * 8 + 2 * t;
        float b0 = bias ? bias[col] * bscale : 0.f;
        float b1 = bias ? bias[col + 1] * bscale : 0.f;
#pragma unroll
        for (int mt = 0; mt < 2; ++mt) {
            const int row = rb + mt * 16 + g;
            *(float2*)(C + (size_t)row * ldc + col) =
                make_float2(acc[mt][nt][0] + b0, acc[mt][nt][1] + b1);
            *(float2*)(C + (size_t)(row + 8) * ldc + col) =
                make_float2(acc[mt][nt][2] + b0, acc[mt][nt][3] + b1);
        }
    }
#undef PREFETCH
}

// ---------------------------------------------------------------------------
// Gather-reduce + a_feats copy:
//   Sh[q,:]       = fp16( sum_k relu(Q[b,idx_k,:] + P[q,:]) * dw_k )
//   out[q, 0:256] = af[q,:]
// ---------------------------------------------------------------------------
__global__ void gather_reduce_copy_kernel(const float* __restrict__ P,
                                          const float* __restrict__ Q,
                                          const int* __restrict__ idx,
                                          const float* __restrict__ dw,
                                          const float* __restrict__ af,
                                          float* __restrict__ out,
                                          __half2* __restrict__ Sh) {
    const int tid = threadIdx.x;
    const int q = blockIdx.x * 4 + (tid >> 6);
    const int l = tid & 63;
    const int b = q >> 13;

    ((float4*)out)[(size_t)q * 128 + l] = ((const float4*)af)[(size_t)q * 64 + l];

    const float4* P4 = (const float4*)P;
    const float4* Q4 = (const float4*)Q + (size_t)b * NB_ * 64;

    const float4 p = P4[(size_t)q * 64 + l];
    float4 acc = make_float4(0.f, 0.f, 0.f, 0.f);

#pragma unroll
    for (int k = 0; k < 8; ++k) {
        const int   j = idx[(size_t)q * 8 + k];
        const float w = dw[(size_t)q * 8 + k];
        const float4 v = Q4[(size_t)j * 64 + l];
        acc.x += fmaxf(v.x + p.x, 0.f) * w;
        acc.y += fmaxf(v.y + p.y, 0.f) * w;
        acc.z += fmaxf(v.z + p.z, 0.f) * w;
        acc.w += fmaxf(v.w + p.w, 0.f) * w;
    }
    Sh[(size_t)q * 128 + 2 * l]     = __floats2half2_rn(acc.x, acc.y);
    Sh[(size_t)q * 128 + 2 * l + 1] = __floats2half2_rn(acc.z, acc.w);
}

// ---------------------------------------------------------------------------
extern "C" void kernel_launch(void* const* d_in, const int* in_sizes, int n_in,
                              void* d_out, int out_size) {
    const float* af = (const float*)d_in[0];
    const float* bf = (const float*)d_in[1];
    const int*   ca = (const int*)d_in[2];
    const int*   cb = (const int*)d_in[3];
    const float* w1 = (const float*)d_in[4];
    const float* b1 = (const float*)d_in[5];
    const float* w2 = (const float*)d_in[6];
    const float* b2 = (const float*)d_in[7];
    float* out = (float*)d_out;

    float *P, *Q, *dw;
    __half *afh, *bfh, *Sh, *Wdh, *W1bh, *W2h;
    int *idx, *ccnt, *cstart, *ccur;
    uint2* pts;
    unsigned* cbp;
    cudaGetSymbolAddress((void**)&P,      g_P);
    cudaGetSymbolAddress((void**)&Q,      g_Q);
    cudaGetSymbolAddress((void**)&afh,    g_afh);
    cudaGetSymbolAddress((void**)&bfh,    g_bfh);
    cudaGetSymbolAddress((void**)&Sh,     g_Sh);
    cudaGetSymbolAddress((void**)&Wdh,    g_Wdh);
    cudaGetSymbolAddress((void**)&W1bh,   g_W1bh);
    cudaGetSymbolAddress((void**)&W2h,    g_W2h);
    cudaGetSymbolAddress((void**)&idx,    g_idx);
    cudaGetSymbolAddress((void**)&dw,     g_dw);
    cudaGetSymbolAddress((void**)&ccnt,   g_cellcnt);
    cudaGetSymbolAddress((void**)&cstart, g_cellstart);
    cudaGetSymbolAddress((void**)&ccur,   g_cellcur);
    cudaGetSymbolAddress((void**)&pts,    g_pts);
    cudaGetSymbolAddress((void**)&cbp,    g_cbp);

    cudaFuncSetAttribute(mma_gemm_kernel,
                         cudaFuncAttributeMaxDynamicSharedMemorySize, GEMM_SMEM);

    const int NTOT = B_ * NA * D_;   // 8,388,608 elements

    // 1. spatial grid build
    zero_cnt_kernel<<<B_, NCELL>>>(ccnt);
    hist_kernel<<<(B_ * NB_) / 256, 256>>>(cb, cbp, ccnt);
    scan_kernel<<<B_, NCELL>>>(ccnt, cstart, ccur);
    scatter_kernel<<<(B_ * NB_) / 256, 256>>>(cbp, ccur, pts);

    // 2. exact certified grid kNN
    knn_grid_kernel<<<dim3(NA / 8, B_), 256>>>(ca, cbp, pts, cstart, idx, dw);

    // 3. fp16 conversions + weight prep
    f32_to_f16_kernel<<<(NTOT / 4) / 256, 256>>>((const float4*)af, (__half2*)afh);
    f32_to_f16_kernel<<<(NTOT / 4) / 256, 256>>>((const float4*)bf, (__half2*)bfh);
    prep_w_kernel<<<256, 256>>>(w1, w2, Wdh, W1bh, W2h);

    // 4. P = af @ W1b^T + b1
    mma_gemm_kernel<<<dim3(2, (B_ * NA) / 64), 256, GEMM_SMEM>>>(afh, W1bh, P, 256, b1, 1.f);

    // 5. Q = bf @ Wd^T
    mma_gemm_kernel<<<dim3(2, (B_ * NB_) / 64), 256, GEMM_SMEM>>>(bfh, Wdh, Q, 256, (const float*)nullptr, 0.f);

    // 6. Sh = fp16(sum_k relu(Q[idx_k] + P) * dw_k) ; out[...,0:256] = af
    gather_reduce_copy_kernel<<<(B_ * NA) / 4, 256>>>(P, Q, idx, dw, af, out, (__half2*)Sh);

    // 7. out[..., 256:512] = Sh @ W2h^T + 8*b2
    mma_gemm_kernel<<<dim3(2, (B_ * NA) / 64), 256, GEMM_SMEM>>>(Sh, W2h, out + 256, 512, b2, 8.f);
}

// round 16
// speedup vs baseline: 1.6667x; 1.0481x over previous
#include <cuda_runtime.h>
#include <cuda_fp16.h>
#include <math.h>
#include <stdint.h>

// Problem shape (fixed for this problem instance)
#define B_    4
#define NA    8192
#define NB_   8192
#define D_    256
#define TOPK  8
#define NCELL 512      // 8x8x8 grid of cells, cell side 16 (in //16 coords)

// ---------------------------------------------------------------------------
// Scratch (static device globals; no dynamic allocation allowed)
// ---------------------------------------------------------------------------
__device__ float  g_P[B_ * NA * D_];       // af @ W1b^T + b1      [32768,256] f32
__device__ __half g_Qh[B_ * NB_ * D_];     // bf @ (W1a-W1b)^T     [32768,256] f16
__device__ __half g_afh[B_ * NA * D_];     // fp16 copy of a_feats
__device__ __half g_bfh[B_ * NB_ * D_];    // fp16 copy of b_feats
__device__ __half g_Sh[B_ * NA * D_];      // gather result, fp16
__device__ __half g_Wdh[D_ * D_];          // [n=d][k=c] = w1[d,c]-w1[d,256+c]
__device__ __half g_W1bh[D_ * D_];         // [n=d][k=c] = w1[d,256+c]
__device__ __half g_W2h[D_ * D_];          // [n=e][k=d] = w2[e,d]
__device__ int    g_idx[B_ * NA * TOPK];
__device__ float  g_dw[B_ * NA * TOPK];

// spatial grid scratch
__device__ int      g_cellcnt[B_ * NCELL];
__device__ int      g_cellstart[B_ * (NCELL + 1)];
__device__ int      g_cellcur[B_ * NCELL];
__device__ uint2    g_pts[B_ * NB_];       // cell-sorted (packed coord, index)
__device__ unsigned g_cbp[B_ * NB_];       // packed //16 coords, original order

// ---------------------------------------------------------------------------
// mma / ldmatrix / cp.async helpers
// ---------------------------------------------------------------------------
__device__ __forceinline__ void mma_f16(float* c,
                                        unsigned a0, unsigned a1, unsigned a2, unsigned a3,
                                        unsigned b0, unsigned b1) {
    asm volatile(
        "mma.sync.aligned.m16n8k16.row.col.f32.f16.f16.f32 "
        "{%0,%1,%2,%3}, {%4,%5,%6,%7}, {%8,%9}, {%0,%1,%2,%3};"
        : "+f"(c[0]), "+f"(c[1]), "+f"(c[2]), "+f"(c[3])
        : "r"(a0), "r"(a1), "r"(a2), "r"(a3), "r"(b0), "r"(b1));
}

#define LDMATRIX_X4(r0, r1, r2, r3, addr) \
    asm volatile("ldmatrix.sync.aligned.m8n8.x4.shared.b16 {%0,%1,%2,%3}, [%4];" \
                 : "=r"(r0), "=r"(r1), "=r"(r2), "=r"(r3) : "r"(addr))

#define CP_ASYNC16(dst_u32, src_ptr) \
    asm volatile("cp.async.cg.shared.global [%0], [%1], 16;" \
                 :: "r"(dst_u32), "l"(src_ptr))
#define CP_COMMIT()  asm volatile("cp.async.commit_group;")
#define CP_WAIT1()   asm volatile("cp.async.wait_group 1;" ::: "memory")
#define CP_WAIT0()   asm volatile("cp.async.wait_group 0;" ::: "memory")

// ---------------------------------------------------------------------------
// fp32 -> fp16 convert for BOTH af and bf in one launch.
// n4 = element count / 4 per array.
// ---------------------------------------------------------------------------
__global__ void f32_to_f16_dual_kernel(const float4* __restrict__ srcA,
                                       const float4* __restrict__ srcB,
                                       __half2* __restrict__ dstA,
                                       __half2* __restrict__ dstB,
                                       int n4) {
    int i = blockIdx.x * blockDim.x + threadIdx.x;
    const float4* src = srcA;
    __half2* dst = dstA;
    if (i >= n4) { i -= n4; src = srcB; dst = dstB; }
    const float4 v = src[i];
    dst[2 * i]     = __floats2half2_rn(v.x, v.y);
    dst[2 * i + 1] = __floats2half2_rn(v.z, v.w);
}

// ---------------------------------------------------------------------------
// Weight preprocessing: fp16 B operands ([n][k] row-major)
// ---------------------------------------------------------------------------
__global__ void prep_w_kernel(const float* __restrict__ w1,
                              const float* __restrict__ w2,
                              __half* __restrict__ Wdh,
                              __half* __restrict__ W1bh,
                              __half* __restrict__ W2h) {
    int d = blockIdx.x;
    int c = threadIdx.x;
    float a = w1[d * 512 + c];
    float b = w1[d * 512 + 256 + c];
    Wdh[d * 256 + c]  = __float2half_rn(a - b);
    W1bh[d * 256 + c] = __float2half_rn(b);
    W2h[d * 256 + c]  = __float2half_rn(w2[d * 256 + c]);
}

// ---------------------------------------------------------------------------
// Spatial grid build: zero -> histogram -> scan -> scatter
// ---------------------------------------------------------------------------
__global__ void zero_cnt_kernel(int* __restrict__ cnt) {
    cnt[blockIdx.x * blockDim.x + threadIdx.x] = 0;
}

__global__ void hist_kernel(const int* __restrict__ coords_b,
                            unsigned* __restrict__ cbp,
                            int* __restrict__ cnt) {
    const int i = blockIdx.x * blockDim.x + threadIdx.x;   // 0..B*NB-1
    const int b = i >> 13;
    const int* cb = coords_b + (size_t)i * 3;
    const unsigned x = ((unsigned)cb[0]) >> 4;
    const unsigned y = ((unsigned)cb[1]) >> 4;
    const unsigned z = ((unsigned)cb[2]) >> 4;
    cbp[i] = x | (y << 8) | (z << 16);
    const int cell = (int)(((x >> 4) << 6) | ((y >> 4) << 3) | (z >> 4));
    atomicAdd(&cnt[b * NCELL + cell], 1);
}

__global__ void scan_kernel(const int* __restrict__ cnt,
                            int* __restrict__ cellstart,
                            int* __restrict__ cur) {
    __shared__ int sc[NCELL];
    const int b = blockIdx.x, t = threadIdx.x;
    const int v = cnt[b * NCELL + t];
    sc[t] = v;
    __syncthreads();
    for (int off = 1; off < NCELL; off <<= 1) {
        int x = (t >= off) ? sc[t - off] : 0;
        __syncthreads();
        sc[t] += x;
        __syncthreads();
    }
    cellstart[b * (NCELL + 1) + t + 1] = sc[t];
    if (t == 0) cellstart[b * (NCELL + 1)] = 0;
    cur[b * NCELL + t] = sc[t] - v;   // exclusive
}

__global__ void scatter_kernel(const unsigned* __restrict__ cbp,
                               int* __restrict__ cur,
                               uint2* __restrict__ pts) {
    const int i = blockIdx.x * blockDim.x + threadIdx.x;
    const int b = i >> 13, j = i & 8191;
    const unsigned p = cbp[i];
    const int cell = (int)((((p >> 4) & 7u) << 6) | (((p >> 12) & 7u) << 3) | ((p >> 20) & 7u));
    const int pos = atomicAdd(&cur[b * NCELL + cell], 1);
    pts[(size_t)b * NB_ + pos] = make_uint2(p, (unsigned)j);
}

// ---------------------------------------------------------------------------
// kNN helpers
// ---------------------------------------------------------------------------
__device__ __forceinline__ void insert8(unsigned best[8], unsigned key) {
    if (key < best[7]) {
        best[7] = key;
#pragma unroll
        for (int t = 7; t > 0; --t) {
            unsigned lo = min(best[t - 1], best[t]);
            unsigned hi = max(best[t - 1], best[t]);
            best[t - 1] = lo;
            best[t]     = hi;
        }
    }
}

__device__ __forceinline__ unsigned merge8(unsigned best[8], int lane) {
    unsigned sel = 0;
#pragma unroll
    for (int r = 0; r < 8; ++r) {
        const unsigned v = best[0];
        const unsigned m = __reduce_min_sync(0xFFFFFFFFu, v);
        if (lane == r) sel = m;
        if (v == m) {
#pragma unroll
            for (int t = 0; t < 7; ++t) best[t] = best[t + 1];
            best[7] = 0xFFFFFFFFu;
        }
    }
    return sel;
}

// ---------------------------------------------------------------------------
// Grid kNN: one warp per query; certified exact (brute fallback if the 8th
// neighbor could lie outside the scanned neighborhood).
// ---------------------------------------------------------------------------
__global__ void knn_grid_kernel(const int* __restrict__ coords_a,
                                const unsigned* __restrict__ cbp,
                                const uint2* __restrict__ pts,
                                const int* __restrict__ cellstart,
                                int* __restrict__ idx_out,
                                float* __restrict__ dw_out) {
    const int b = blockIdx.y;
    const int warp = threadIdx.x >> 5;
    const int lane = threadIdx.x & 31;
    const int n = blockIdx.x * 8 + warp;

    const int* ca = coords_a + ((size_t)b * NA + n) * 3;
    const unsigned qx = ((unsigned)ca[0]) >> 4;
    const unsigned qy = ((unsigned)ca[1]) >> 4;
    const unsigned qz = ((unsigned)ca[2]) >> 4;
    const unsigned qp = qx | (qy << 8) | (qz << 16);

    const int cx = (int)(qx >> 4), cy = (int)(qy >> 4), cz = (int)(qz >> 4);
    const int x0 = max(cx - 1, 0), x1 = min(cx + 1, 7);
    const int y0 = max(cy - 1, 0), y1 = min(cy + 1, 7);
    const int z0 = max(cz - 1, 0), z1 = min(cz + 1, 7);

    const int sbase = b * (NCELL + 1);
    const uint2* ptsb = pts + (size_t)b * NB_;

    unsigned best[8];
#pragma unroll
    for (int t = 0; t < 8; ++t) best[t] = 0xFFFFFFFFu;

    for (int x = x0; x <= x1; ++x)
        for (int y = y0; y <= y1; ++y)
            for (int z = z0; z <= z1; ++z) {
                const int c = (x << 6) | (y << 3) | z;
                const int s = __ldg(&cellstart[sbase + c]);
                const int e = __ldg(&cellstart[sbase + c + 1]);
                for (int o = s + lane; o < e; o += 32) {
                    const uint2 pt = ptsb[o];
                    const unsigned ad = __vabsdiffu4(pt.x, qp);
                    const unsigned d2 = (unsigned)__dp4a((int)ad, (int)ad, 0);
                    insert8(best, (d2 << 13) | pt.y);
                }
            }

    unsigned sel = merge8(best, lane);

    const unsigned d2_8 = __shfl_sync(0xFFFFFFFFu, sel, 7) >> 13;
    int mo = 0x7FFFFFFF;
    if (x0 > 0) { int d = (int)qx - (16 * x0 - 1); mo = min(mo, d * d); }
    if (x1 < 7) { int d = 16 * (x1 + 1) - (int)qx; mo = min(mo, d * d); }
    if (y0 > 0) { int d = (int)qy - (16 * y0 - 1); mo = min(mo, d * d); }
    if (y1 < 7) { int d = 16 * (y1 + 1) - (int)qy; mo = min(mo, d * d); }
    if (z0 > 0) { int d = (int)qz - (16 * z0 - 1); mo = min(mo, d * d); }
    if (z1 < 7) { int d = 16 * (z1 + 1) - (int)qz; mo = min(mo, d * d); }

    if (d2_8 >= (unsigned)mo) {   // warp-uniform; vanishingly rare
#pragma unroll
        for (int t = 0; t < 8; ++t) best[t] = 0xFFFFFFFFu;
        const unsigned* cb = cbp + (size_t)b * NB_;
        for (int j = lane; j < NB_; j += 32) {
            const unsigned p = __ldg(&cb[j]);
            const unsigned ad = __vabsdiffu4(p, qp);
            const unsigned d2 = (unsigned)__dp4a((int)ad, (int)ad, 0);
            insert8(best, (d2 << 13) | (unsigned)j);
        }
        sel = merge8(best, lane);
    }

    if (lane < 8) {
        const int j = (int)(sel & 8191u);
        const float dist = sqrtf((float)(sel >> 13)) * (1.0f / 128.0f);
        const float dwv = 0.5f - fminf(dist, 0.5f);
        const size_t o = ((size_t)b * NA + n) * 8 + lane;
        idx_out[o] = j;
        dw_out[o]  = dwv;
    }
}

// ---------------------------------------------------------------------------
// FP16 ldmatrix GEMM (dual-mode): C = A @ B^T, fp32 accum.
//   grid (2, M/64, Z). z=0: A0/B0 -> f32 C0 (ldc0, +bscale0*bias0).
//                      z=1: A1/B1 -> f16 C1 (ldc 256, no bias).
//   Tile 64x128; 256 threads as 2(m) x 4(n) warps; warp tile 32x32; BK=64.
//   Smem fp16, row stride 72 halves (144B): conflict-free ldmatrix phases.
// ---------------------------------------------------------------------------
#define SRH   72                  // smem row stride in halves
#define A_STB (64 * SRH * 2)      // 9216 B per A stage
#define B_STB (128 * SRH * 2)     // 18432 B per B stage
#define GEMM_SMEM (2 * (A_STB + B_STB))   // 55296 B

__global__ __launch_bounds__(256, 3)
void mma_gemm_kernel(const __half* __restrict__ A0, const __half* __restrict__ B0,
                     float* __restrict__ C0, int ldc0,
                     const float* __restrict__ bias0, float bscale0,
                     const __half* __restrict__ A1, const __half* __restrict__ B1,
                     __half* __restrict__ C1) {
    extern __shared__ char smc[];
    const uint32_t smA = (uint32_t)__cvta_generic_to_shared(smc);
    const uint32_t smB = smA + 2 * A_STB;

    const int tid  = threadIdx.x;
    const int wid  = tid >> 5;
    const int lane = tid & 31;
    const int g    = lane >> 2;   // groupID 0..7
    const int t    = lane & 3;    // 0..3
    const int wm   = wid >> 2;    // 0..1 (32 rows each)
    const int wn   = wid & 3;     // 0..3 (32 cols each)
    const int z    = blockIdx.z;

    const __half* Ah = (z == 0) ? A0 : A1;
    const __half* Bh = (z == 0) ? B0 : B1;

    const __half* Ap = Ah + (size_t)blockIdx.y * 64 * 256;
    const __half* Bp = Bh + (size_t)blockIdx.x * 128 * 256;

    const int arow0 = tid >> 3,           ac0 = (tid & 7) * 8;
    const int arow1 = (tid + 256) >> 3,   ac1 = ac0;

    const int sel = lane >> 3;            // 0..3 (x4 tile select)
    const int lr  = lane & 7;             // row within tile
    const int a_row_off = (sel & 1) * 8 + lr;
    const int a_k_off   = (sel >> 1) * 8;
    const int b_n_off = (sel >> 1) * 8 + lr;
    const int b_k_off = (sel & 1) * 8;

    float acc[2][4][4];
#pragma unroll
    for (int i = 0; i < 2; ++i)
#pragma unroll
        for (int j = 0; j < 4; ++j)
#pragma unroll
            for (int r = 0; r < 4; ++r) acc[i][j][r] = 0.f;

#define PREFETCH(s) do {                                                        \
    const int k0_ = (s) * 64;                                                   \
    const uint32_t ab_ = smA + ((s) & 1) * A_STB;                               \
    const uint32_t bb_ = smB + ((s) & 1) * B_STB;                               \
    CP_ASYNC16(ab_ + (arow0 * SRH + ac0) * 2, Ap + (size_t)arow0 * 256 + k0_ + ac0); \
    CP_ASYNC16(ab_ + (arow1 * SRH + ac1) * 2, Ap + (size_t)arow1 * 256 + k0_ + ac1); \
    _Pragma("unroll")                                                           \
    for (int i_ = 0; i_ < 4; ++i_) {                                            \
        const int id_ = tid + 256 * i_;                                         \
        const int br_ = id_ >> 3, bc_ = (id_ & 7) * 8;                          \
        CP_ASYNC16(bb_ + (br_ * SRH + bc_) * 2, Bp + (size_t)br_ * 256 + k0_ + bc_); \
    }                                                                           \
} while (0)

    PREFETCH(0);
    CP_COMMIT();

    for (int s = 0; s < 4; ++s) {
        if (s < 3) {
            PREFETCH(s + 1);
            CP_COMMIT();
            CP_WAIT1();
        } else {
            CP_WAIT0();
        }
        __syncthreads();

        const uint32_t as = smA + (s & 1) * A_STB;
        const uint32_t bs = smB + (s & 1) * B_STB;

#pragma unroll
        for (int ks = 0; ks < 4; ++ks) {
            unsigned fb0[4], fb1[4];
#pragma unroll
            for (int p = 0; p < 2; ++p) {
                const int nrow = wn * 32 + p * 16 + b_n_off;
                const uint32_t addr = bs + (nrow * SRH + ks * 16 + b_k_off) * 2;
                unsigned r0, r1, r2, r3;
                LDMATRIX_X4(r0, r1, r2, r3, addr);
                fb0[2 * p]     = r0;  fb1[2 * p]     = r1;
                fb0[2 * p + 1] = r2;  fb1[2 * p + 1] = r3;
            }
#pragma unroll
            for (int mt = 0; mt < 2; ++mt) {
                const int arow = wm * 32 + mt * 16 + a_row_off;
                const uint32_t addr = as + (arow * SRH + ks * 16 + a_k_off) * 2;
                unsigned a0, a1, a2, a3;
                LDMATRIX_X4(a0, a1, a2, a3, addr);
#pragma unroll
                for (int nt = 0; nt < 4; ++nt)
                    mma_f16(acc[mt][nt], a0, a1, a2, a3, fb0[nt], fb1[nt]);
            }
        }
        __syncthreads();
    }

    // epilogue
    const int rb = blockIdx.y * 64 + wm * 32;
    const int cb = blockIdx.x * 128 + wn * 32;
    if (z == 0) {
#pragma unroll
        for (int nt = 0; nt < 4; ++nt) {
            const int col = cb + nt * 8 + 2 * t;
            float b0 = bias0 ? bias0[col] * bscale0 : 0.f;
            float b1 = bias0 ? bias0[col + 1] * bscale0 : 0.f;
#pragma unroll
            for (int mt = 0; mt < 2; ++mt) {
                const int row = rb + mt * 16 + g;
                *(float2*)(C0 + (size_t)row * ldc0 + col) =
                    make_float2(acc[mt][nt][0] + b0, acc[mt][nt][1] + b1);
                *(float2*)(C0 + (size_t)(row + 8) * ldc0 + col) =
                    make_float2(acc[mt][nt][2] + b0, acc[mt][nt][3] + b1);
            }
        }
    } else {
#pragma unroll
        for (int nt = 0; nt < 4; ++nt) {
            const int col = cb + nt * 8 + 2 * t;
#pragma unroll
            for (int mt = 0; mt < 2; ++mt) {
                const int row = rb + mt * 16 + g;
                *(__half2*)(C1 + (size_t)row * 256 + col) =
                    __floats2half2_rn(acc[mt][nt][0], acc[mt][nt][1]);
                *(__half2*)(C1 + (size_t)(row + 8) * 256 + col) =
                    __floats2half2_rn(acc[mt][nt][2], acc[mt][nt][3]);
            }
        }
    }
#undef PREFETCH
}

// ---------------------------------------------------------------------------
// Gather-reduce + a_feats copy:
//   Sh[q,:]       = fp16( sum_k relu(f32(Qh[b,idx_k,:]) + P[q,:]) * dw_k )
//   out[q, 0:256] = af[q,:]
// Qh is fp16: 8B load per 4 channels (half the L2 traffic of f32 Q).
// ---------------------------------------------------------------------------
__global__ void gather_reduce_copy_kernel(const float* __restrict__ P,
                                          const __half* __restrict__ Qh,
                                          const int* __restrict__ idx,
                                          const float* __restrict__ dw,
                                          const float* __restrict__ af,
                                          float* __restrict__ out,
                                          __half2* __restrict__ Sh) {
    const int tid = threadIdx.x;
    const int q = blockIdx.x * 4 + (tid >> 6);
    const int l = tid & 63;
    const int b = q >> 13;

    ((float4*)out)[(size_t)q * 128 + l] = ((const float4*)af)[(size_t)q * 64 + l];

    const float4* P4 = (const float4*)P;
    const uint2* Q8 = (const uint2*)(Qh + (size_t)b * NB_ * 256);  // 4 halves per entry

    const float4 p = P4[(size_t)q * 64 + l];
    float4 acc = make_float4(0.f, 0.f, 0.f, 0.f);

#pragma unroll
    for (int k = 0; k < 8; ++k) {
        const int   j = idx[(size_t)q * 8 + k];
        const float w = dw[(size_t)q * 8 + k];
        const uint2 raw = Q8[(size_t)j * 64 + l];
        const float2 f01 = __half22float2(*reinterpret_cast<const __half2*>(&raw.x));
        const float2 f23 = __half22float2(*reinterpret_cast<const __half2*>(&raw.y));
        acc.x += fmaxf(f01.x + p.x, 0.f) * w;
        acc.y += fmaxf(f01.y + p.y, 0.f) * w;
        acc.z += fmaxf(f23.x + p.z, 0.f) * w;
        acc.w += fmaxf(f23.y + p.w, 0.f) * w;
    }
    Sh[(size_t)q * 128 + 2 * l]     = __floats2half2_rn(acc.x, acc.y);
    Sh[(size_t)q * 128 + 2 * l + 1] = __floats2half2_rn(acc.z, acc.w);
}

// ---------------------------------------------------------------------------
extern "C" void kernel_launch(void* const* d_in, const int* in_sizes, int n_in,
                              void* d_out, int out_size) {
    const float* af = (const float*)d_in[0];
    const float* bf = (const float*)d_in[1];
    const int*   ca = (const int*)d_in[2];
    const int*   cb = (const int*)d_in[3];
    const float* w1 = (const float*)d_in[4];
    const float* b1 = (const float*)d_in[5];
    const float* w2 = (const float*)d_in[6];
    const float* b2 = (const float*)d_in[7];
    float* out = (float*)d_out;

    float *P, *dw;
    __half *Qh, *afh, *bfh, *Sh, *Wdh, *W1bh, *W2h;
    int *idx, *ccnt, *cstart, *ccur;
    uint2* pts;
    unsigned* cbp;
    cudaGetSymbolAddress((void**)&P,      g_P);
    cudaGetSymbolAddress((void**)&Qh,     g_Qh);
    cudaGetSymbolAddress((void**)&afh,    g_afh);
    cudaGetSymbolAddress((void**)&bfh,    g_bfh);
    cudaGetSymbolAddress((void**)&Sh,     g_Sh);
    cudaGetSymbolAddress((void**)&Wdh,    g_Wdh);
    cudaGetSymbolAddress((void**)&W1bh,   g_W1bh);
    cudaGetSymbolAddress((void**)&W2h,    g_W2h);
    cudaGetSymbolAddress((void**)&idx,    g_idx);
    cudaGetSymbolAddress((void**)&dw,     g_dw);
    cudaGetSymbolAddress((void**)&ccnt,   g_cellcnt);
    cudaGetSymbolAddress((void**)&cstart, g_cellstart);
    cudaGetSymbolAddress((void**)&ccur,   g_cellcur);
    cudaGetSymbolAddress((void**)&pts,    g_pts);
    cudaGetSymbolAddress((void**)&cbp,    g_cbp);

    cudaFuncSetAttribute(mma_gemm_kernel,
                         cudaFuncAttributeMaxDynamicSharedMemorySize, GEMM_SMEM);

    const int NTOT = B_ * NA * D_;   // 8,388,608 elements

    // 1. spatial grid build
    zero_cnt_kernel<<<B_, NCELL>>>(ccnt);
    hist_kernel<<<(B_ * NB_) / 256, 256>>>(cb, cbp, ccnt);
    scan_kernel<<<B_, NCELL>>>(ccnt, cstart, ccur);
    scatter_kernel<<<(B_ * NB_) / 256, 256>>>(cbp, ccur, pts);

    // 2. exact certified grid kNN
    knn_grid_kernel<<<dim3(NA / 8, B_), 256>>>(ca, cbp, pts, cstart, idx, dw);

    // 3. fp16 conversions (af + bf in one launch) + weight prep
    f32_to_f16_dual_kernel<<<2 * (NTOT / 4) / 256, 256>>>(
        (const float4*)af, (const float4*)bf, (__half2*)afh, (__half2*)bfh, NTOT / 4);
    prep_w_kernel<<<256, 256>>>(w1, w2, Wdh, W1bh, W2h);

    // 4+5. fused: z=0 -> P = af @ W1b^T + b1 (f32); z=1 -> Qh = bf @ Wd^T (f16)
    mma_gemm_kernel<<<dim3(2, (B_ * NA) / 64, 2), 256, GEMM_SMEM>>>(
        afh, W1bh, P, 256, b1, 1.f, bfh, Wdh, Qh);

    // 6. Sh = fp16(sum_k relu(Qh[idx_k] + P) * dw_k) ; out[...,0:256] = af
    gather_reduce_copy_kernel<<<(B_ * NA) / 4, 256>>>(P, Qh, idx, dw, af, out, (__half2*)Sh);

    // 7. out[..., 256:512] = Sh @ W2h^T + 8*b2
    mma_gemm_kernel<<<dim3(2, (B_ * NA) / 64, 1), 256, GEMM_SMEM>>>(
        Sh, W2h, out + 256, 512, b2, 8.f, (const __half*)nullptr, (const __half*)nullptr,
        (__half*)nullptr);
}